// round 1
// baseline (speedup 1.0000x reference)
#include <cuda_runtime.h>
#include <math.h>

#define NN 50000
#define NE 300000
#define HID 256
#define NLAYER 4
#define NG 1024
#define NODE_DIM 11
#define EDGE_DIM 5
#define NB_BN ((NN + 255) / 256)   // 196

// ---------------- persistent scratch (device globals; no allocation) ----------------
__device__ float d_h[NN * HID];     // node features
__device__ float d_z[NN * HID];     // aggregation out / MLP out
__device__ float d_t[NN * HID];     // MLP hidden
__device__ int   d_cnt[NN];         // degree counts / scatter cursor
__device__ int   d_rowptr[NN + 1];
__device__ int   d_eids[NE];
__device__ float d_psum[NB_BN * HID];
__device__ float d_psq[NB_BN * HID];
__device__ float d_scale[HID];
__device__ float d_shift[HID];
__device__ int   d_gcnt[NG];
__device__ int   d_gstart[NG + 1];
__device__ float d_gfeat[NG * 3 * HID];
__device__ float d_h1[NG * HID];
__device__ float d_h2[NG * (HID / 2)];

// ---------------- CSR build ----------------
__global__ void k_zero_cnt() {
    int i = blockIdx.x * blockDim.x + threadIdx.x;
    if (i < NN) d_cnt[i] = 0;
}

__global__ void k_count(const int* __restrict__ ei) {
    int e = blockIdx.x * blockDim.x + threadIdx.x;
    if (e < NE) atomicAdd(&d_cnt[ei[NE + e]], 1);
}

__global__ void k_scan_nodes() {
    __shared__ int buf[1024];
    __shared__ int carry;
    int tid = threadIdx.x;
    if (tid == 0) carry = 0;
    __syncthreads();
    for (int base = 0; base < NN; base += 1024) {
        int v = (base + tid < NN) ? d_cnt[base + tid] : 0;
        buf[tid] = v;
        __syncthreads();
        for (int off = 1; off < 1024; off <<= 1) {
            int t = (tid >= off) ? buf[tid - off] : 0;
            __syncthreads();
            buf[tid] += t;
            __syncthreads();
        }
        int excl = buf[tid] - v + carry;
        if (base + tid < NN) { d_rowptr[base + tid] = excl; d_cnt[base + tid] = excl; }
        __syncthreads();
        if (tid == 0) carry += buf[1023];
        __syncthreads();
    }
    if (tid == 0) d_rowptr[NN] = carry;
}

__global__ void k_scatter(const int* __restrict__ ei) {
    int e = blockIdx.x * blockDim.x + threadIdx.x;
    if (e < NE) {
        int pos = atomicAdd(&d_cnt[ei[NE + e]], 1);
        d_eids[pos] = e;
    }
}

// deterministic order: sort each row's edge ids (avg degree 6)
__global__ void k_sortrows() {
    int i = blockIdx.x * blockDim.x + threadIdx.x;
    if (i >= NN) return;
    int rs = d_rowptr[i], re = d_rowptr[i + 1];
    for (int a = rs + 1; a < re; a++) {
        int key = d_eids[a];
        int b = a - 1;
        while (b >= rs && d_eids[b] > key) { d_eids[b + 1] = d_eids[b]; b--; }
        d_eids[b + 1] = key;
    }
}

// ---------------- encoder: h = relu(x @ enc_W + enc_b) ----------------
#define ENC_NPB 64
__global__ void k_encoder(const float* __restrict__ x, const float* __restrict__ W,
                          const float* __restrict__ b) {
    __shared__ float Ws[NODE_DIM][HID];
    __shared__ float bs[HID];
    int c = threadIdx.x;
    #pragma unroll
    for (int k = 0; k < NODE_DIM; k++) Ws[k][c] = W[k * HID + c];
    bs[c] = b[c];
    __syncthreads();
    int n0 = blockIdx.x * ENC_NPB;
    for (int i = 0; i < ENC_NPB; i++) {
        int n = n0 + i;
        if (n >= NN) break;
        float acc = bs[c];
        #pragma unroll
        for (int k = 0; k < NODE_DIM; k++) acc += __ldg(&x[n * NODE_DIM + k]) * Ws[k][c];
        d_h[n * HID + c] = fmaxf(acc, 0.f);
    }
}

// ---------------- GINE aggregation: z = h + sum_e relu(h[src] + e) ----------------
__global__ void k_aggregate(const int* __restrict__ ei, const float* __restrict__ ea,
                            const float* __restrict__ eW, const float* __restrict__ eb) {
    __shared__ float Ws[EDGE_DIM][HID];
    __shared__ float bs[HID];
    int c = threadIdx.x;
    #pragma unroll
    for (int k = 0; k < EDGE_DIM; k++) Ws[k][c] = eW[k * HID + c];
    bs[c] = eb[c];
    __syncthreads();
    int n0 = blockIdx.x * 8;
    for (int i = 0; i < 8; i++) {
        int n = n0 + i;
        if (n >= NN) break;
        int rs = d_rowptr[n], re = d_rowptr[n + 1];
        float acc = d_h[n * HID + c];
        for (int p = rs; p < re; p++) {
            int e = d_eids[p];
            int src = ei[e];
            float ec = bs[c];
            #pragma unroll
            for (int k = 0; k < EDGE_DIM; k++) ec += __ldg(&ea[e * EDGE_DIM + k]) * Ws[k][c];
            acc += fmaxf(d_h[src * HID + c] + ec, 0.f);
        }
        d_z[n * HID + c] = acc;
    }
}

// ---------------- SGEMM: C[M,256] = act(A[M,256] @ B[256,256] + bias) ----------------
// 128x128 tile, BK=16, 256 threads, 8x8 per thread
template <bool RELU>
__global__ void k_sgemm(const float* __restrict__ A, const float* __restrict__ B,
                        const float* __restrict__ bias, float* __restrict__ C, int M) {
    __shared__ float As[16][128];
    __shared__ float Bs[16][128];
    int tid = threadIdx.x;
    int bm = blockIdx.y * 128, bn = blockIdx.x * 128;
    int tx = tid & 15, ty = tid >> 4;
    float acc[8][8];
    #pragma unroll
    for (int i = 0; i < 8; i++)
        #pragma unroll
        for (int j = 0; j < 8; j++) acc[i][j] = 0.f;

    int arow = tid >> 1, acg = (tid & 1) * 8;   // A: 1 row, 8 cols per thread
    int bk = tid >> 4, bnn = (tid & 15) * 8;    // B: 1 row, 8 cols per thread

    for (int k0 = 0; k0 < 256; k0 += 16) {
        int gm = bm + arow;
        if (gm < M) {
            float4 v0 = *(const float4*)&A[gm * 256 + k0 + acg];
            float4 v1 = *(const float4*)&A[gm * 256 + k0 + acg + 4];
            As[acg + 0][arow] = v0.x; As[acg + 1][arow] = v0.y;
            As[acg + 2][arow] = v0.z; As[acg + 3][arow] = v0.w;
            As[acg + 4][arow] = v1.x; As[acg + 5][arow] = v1.y;
            As[acg + 6][arow] = v1.z; As[acg + 7][arow] = v1.w;
        }
        float4 w0 = *(const float4*)&B[(k0 + bk) * 256 + bn + bnn];
        float4 w1 = *(const float4*)&B[(k0 + bk) * 256 + bn + bnn + 4];
        *(float4*)&Bs[bk][bnn] = w0;
        *(float4*)&Bs[bk][bnn + 4] = w1;
        __syncthreads();
        #pragma unroll
        for (int k = 0; k < 16; k++) {
            float a[8], b[8];
            #pragma unroll
            for (int i = 0; i < 8; i++) a[i] = As[k][ty * 8 + i];
            #pragma unroll
            for (int j = 0; j < 8; j++) b[j] = Bs[k][tx * 8 + j];
            #pragma unroll
            for (int i = 0; i < 8; i++)
                #pragma unroll
                for (int j = 0; j < 8; j++) acc[i][j] += a[i] * b[j];
        }
        __syncthreads();
    }
    #pragma unroll
    for (int i = 0; i < 8; i++) {
        int gm = bm + ty * 8 + i;
        if (gm >= M) continue;
        #pragma unroll
        for (int j = 0; j < 8; j += 4) {
            int gn = bn + tx * 8 + j;
            float4 r;
            r.x = acc[i][j + 0] + bias[gn + 0];
            r.y = acc[i][j + 1] + bias[gn + 1];
            r.z = acc[i][j + 2] + bias[gn + 2];
            r.w = acc[i][j + 3] + bias[gn + 3];
            if (RELU) {
                r.x = fmaxf(r.x, 0.f); r.y = fmaxf(r.y, 0.f);
                r.z = fmaxf(r.z, 0.f); r.w = fmaxf(r.w, 0.f);
            }
            *(float4*)&C[gm * 256 + gn] = r;
        }
    }
}

// ---------------- BatchNorm (deterministic two-level reduction) ----------------
__global__ void k_bn_partial() {
    int c = threadIdx.x;
    int n0 = blockIdx.x * 256;
    float s = 0.f, s2 = 0.f;
    for (int i = 0; i < 256; i++) {
        int n = n0 + i;
        if (n >= NN) break;
        float v = d_z[n * HID + c];
        s += v; s2 += v * v;
    }
    d_psum[blockIdx.x * HID + c] = s;
    d_psq[blockIdx.x * HID + c] = s2;
}

__global__ void k_bn_final(const float* __restrict__ g, const float* __restrict__ b) {
    int c = threadIdx.x;
    float s = 0.f, s2 = 0.f;
    for (int blk = 0; blk < NB_BN; blk++) {
        s += d_psum[blk * HID + c];
        s2 += d_psq[blk * HID + c];
    }
    float mu = s / (float)NN;
    float var = s2 / (float)NN - mu * mu;
    float sc = g[c] * rsqrtf(var + 1e-5f);
    d_scale[c] = sc;
    d_shift[c] = b[c] - mu * sc;
}

__global__ void k_bn_apply() {
    int idx = blockIdx.x * blockDim.x + threadIdx.x;
    if (idx >= NN * HID) return;
    int c = idx & (HID - 1);
    float v = d_z[idx] * d_scale[c] + d_shift[c];
    d_h[idx] = fmaxf(v, 0.f) + d_h[idx];
}

// ---------------- graph pooling ----------------
__global__ void k_zero_gcnt() {
    int i = blockIdx.x * blockDim.x + threadIdx.x;
    if (i < NG) d_gcnt[i] = 0;
}

__global__ void k_gcount(const int* __restrict__ batch) {
    int n = blockIdx.x * blockDim.x + threadIdx.x;
    if (n < NN) atomicAdd(&d_gcnt[batch[n]], 1);
}

__global__ void k_gscan() {
    __shared__ int buf[1024];
    int tid = threadIdx.x;
    int v = d_gcnt[tid];
    buf[tid] = v;
    __syncthreads();
    for (int off = 1; off < 1024; off <<= 1) {
        int t = (tid >= off) ? buf[tid - off] : 0;
        __syncthreads();
        buf[tid] += t;
        __syncthreads();
    }
    d_gstart[tid + 1] = buf[tid];
    if (tid == 0) d_gstart[0] = 0;
}

__global__ void k_pool() {
    int g = blockIdx.x, c = threadIdx.x;
    int s0 = d_gstart[g], s1 = d_gstart[g + 1];
    float sum = 0.f;
    float mx = -INFINITY;
    for (int n = s0; n < s1; n++) {
        float v = d_h[n * HID + c];
        sum += v;
        mx = fmaxf(mx, v);
    }
    float cntf = (float)(s1 - s0);
    float mean = sum / fmaxf(cntf, 1.f);
    d_gfeat[g * 768 + c] = mean;
    d_gfeat[g * 768 + 256 + c] = sum;
    d_gfeat[g * 768 + 512 + c] = mx;
}

// ---------------- head ----------------
__global__ void k_head1(const float* __restrict__ W, const float* __restrict__ b) {
    __shared__ float gs[8][768];
    int tid = threadIdx.x;
    int g0 = blockIdx.x * 8;
    for (int j = 0; j < 8; j++)
        for (int idx = tid; idx < 768; idx += 256)
            gs[j][idx] = d_gfeat[(g0 + j) * 768 + idx];
    __syncthreads();
    int c = tid;
    float acc[8];
    float bv = b[c];
    #pragma unroll
    for (int j = 0; j < 8; j++) acc[j] = bv;
    for (int k = 0; k < 768; k++) {
        float w = W[k * 256 + c];
        #pragma unroll
        for (int j = 0; j < 8; j++) acc[j] += gs[j][k] * w;
    }
    #pragma unroll
    for (int j = 0; j < 8; j++) d_h1[(g0 + j) * 256 + c] = fmaxf(acc[j], 0.f);
}

__global__ void k_head2(const float* __restrict__ W, const float* __restrict__ b) {
    __shared__ float hs[8][256];
    int tid = threadIdx.x;  // 128 threads
    int g0 = blockIdx.x * 8;
    for (int j = 0; j < 8; j++)
        for (int idx = tid; idx < 256; idx += 128)
            hs[j][idx] = d_h1[(g0 + j) * 256 + idx];
    __syncthreads();
    int c = tid;
    float acc[8];
    float bv = b[c];
    #pragma unroll
    for (int j = 0; j < 8; j++) acc[j] = bv;
    for (int k = 0; k < 256; k++) {
        float w = W[k * 128 + c];
        #pragma unroll
        for (int j = 0; j < 8; j++) acc[j] += hs[j][k] * w;
    }
    #pragma unroll
    for (int j = 0; j < 8; j++) d_h2[(g0 + j) * 128 + c] = fmaxf(acc[j], 0.f);
}

__global__ void k_head3(const float* __restrict__ W, const float* __restrict__ b,
                        float* __restrict__ out) {
    int w = threadIdx.x >> 5, lane = threadIdx.x & 31;
    int g = blockIdx.x * 8 + w;
    float s = 0.f;
    for (int k = lane; k < 128; k += 32)
        s += d_h2[g * 128 + k] * __ldg(&W[k]);
    #pragma unroll
    for (int off = 16; off; off >>= 1) s += __shfl_xor_sync(0xffffffffu, s, off);
    if (lane == 0) out[g] = s + __ldg(&b[0]);
}

// ---------------- launch ----------------
extern "C" void kernel_launch(void* const* d_in, const int* in_sizes, int n_in,
                              void* d_out, int out_size) {
    const float* x      = (const float*)d_in[0];
    const int*   ei     = (const int*)d_in[1];
    const float* ea     = (const float*)d_in[2];
    const int*   batch  = (const int*)d_in[3];
    const float* enc_W  = (const float*)d_in[4];
    const float* enc_b  = (const float*)d_in[5];
    const float* edge_W = (const float*)d_in[6];
    const float* edge_b = (const float*)d_in[7];
    const float* mlp_W1 = (const float*)d_in[8];
    const float* mlp_b1 = (const float*)d_in[9];
    const float* mlp_W2 = (const float*)d_in[10];
    const float* mlp_b2 = (const float*)d_in[11];
    const float* bn_g   = (const float*)d_in[12];
    const float* bn_b   = (const float*)d_in[13];
    const float* hW1    = (const float*)d_in[14];
    const float* hb1    = (const float*)d_in[15];
    const float* hW2    = (const float*)d_in[16];
    const float* hb2    = (const float*)d_in[17];
    const float* hW3    = (const float*)d_in[18];
    const float* hb3    = (const float*)d_in[19];
    float* out = (float*)d_out;

    static float *p_h = nullptr, *p_z = nullptr, *p_t = nullptr;
    if (!p_h) {
        cudaGetSymbolAddress((void**)&p_h, d_h);
        cudaGetSymbolAddress((void**)&p_z, d_z);
        cudaGetSymbolAddress((void**)&p_t, d_t);
    }

    // CSR build (deterministic)
    k_zero_cnt<<<(NN + 255) / 256, 256>>>();
    k_count<<<(NE + 255) / 256, 256>>>(ei);
    k_scan_nodes<<<1, 1024>>>();
    k_scatter<<<(NE + 255) / 256, 256>>>(ei);
    k_sortrows<<<(NN + 255) / 256, 256>>>();

    // encoder
    k_encoder<<<(NN + ENC_NPB - 1) / ENC_NPB, 256>>>(x, enc_W, enc_b);

    dim3 gemm_grid(2, (NN + 127) / 128);
    for (int l = 0; l < NLAYER; l++) {
        k_aggregate<<<(NN + 7) / 8, 256>>>(ei, ea, edge_W + l * EDGE_DIM * HID,
                                           edge_b + l * HID);
        k_sgemm<true><<<gemm_grid, 256>>>(p_z, mlp_W1 + l * HID * HID,
                                          mlp_b1 + l * HID, p_t, NN);
        k_sgemm<false><<<gemm_grid, 256>>>(p_t, mlp_W2 + l * HID * HID,
                                           mlp_b2 + l * HID, p_z, NN);
        k_bn_partial<<<NB_BN, 256>>>();
        k_bn_final<<<1, 256>>>(bn_g + l * HID, bn_b + l * HID);
        k_bn_apply<<<(NN * HID + 255) / 256, 256>>>();
    }

    // pooling + head
    k_zero_gcnt<<<(NG + 255) / 256, 256>>>();
    k_gcount<<<(NN + 255) / 256, 256>>>(batch);
    k_gscan<<<1, 1024>>>();
    k_pool<<<NG, 256>>>();
    k_head1<<<NG / 8, 256>>>(hW1, hb1);
    k_head2<<<NG / 8, 128>>>(hW2, hb2);
    k_head3<<<NG / 8, 256>>>(hW3, hb3, out);
}

// round 3
// speedup vs baseline: 1.5579x; 1.5579x over previous
#include <cuda_runtime.h>
#include <cuda_bf16.h>
#include <math.h>
#include <stdint.h>

#define NN 50000
#define NE 300000
#define HID 256
#define NLAYER 4
#define NG 1024
#define NODE_DIM 11
#define EDGE_DIM 5
#define NB_BN ((NN + 255) / 256)   // 196

// ---------------- persistent scratch (device globals; no allocation) ----------------
__device__ __align__(16) float d_h[NN * HID];
__device__ __align__(16) float d_z[NN * HID];            // GEMM2 out (fp32, for BN)
__device__ __align__(16) __nv_bfloat16 d_zhi[NN * HID];  // GEMM1 input hi
__device__ __align__(16) __nv_bfloat16 d_zlo[NN * HID];
__device__ __align__(16) __nv_bfloat16 d_thi[NN * HID];  // GEMM2 input hi
__device__ __align__(16) __nv_bfloat16 d_tlo[NN * HID];
__device__ __align__(16) __nv_bfloat16 d_Wc[NLAYER * 2 * 2 * HID * HID]; // [l][mat][hl][n][k]
__device__ int   d_cnt[NN];
__device__ int   d_rowptr[NN + 1];
__device__ int   d_eids[NE];
__device__ float d_psum[NB_BN * HID];
__device__ float d_psq[NB_BN * HID];
__device__ float d_scale[HID];
__device__ float d_shift[HID];
__device__ int   d_gcnt[NG];
__device__ int   d_gstart[NG + 1];
__device__ float d_gfeat[NG * 3 * HID];
__device__ float d_h1[NG * HID];
__device__ float d_h2[NG * (HID / 2)];

// ================= portable PTX helpers (sm_80+ baseline; NO tcgen05) =================
__device__ __forceinline__ uint32_t smem_u32(const void* p) {
    uint32_t a;
    asm("{ .reg .u64 t; cvta.to.shared.u64 t, %1; cvt.u32.u64 %0, t; }" : "=r"(a) : "l"(p));
    return a;
}
#define SW128(x) ((x) ^ (((x) >> 3) & 0x70))

__device__ __forceinline__ void cp16(uint32_t dst, const void* src, int srcbytes) {
    asm volatile("cp.async.cg.shared.global [%0], [%1], 16, %2;"
                 :: "r"(dst), "l"(src), "r"(srcbytes) : "memory");
}
#define CP_COMMIT() asm volatile("cp.async.commit_group;" ::: "memory")
#define CP_WAIT0()  asm volatile("cp.async.wait_group 0;" ::: "memory")
#define CP_WAIT1()  asm volatile("cp.async.wait_group 1;" ::: "memory")

__device__ __forceinline__ void ldsm4(uint32_t* r, uint32_t addr) {
    asm volatile("ldmatrix.sync.aligned.m8n8.x4.shared.b16 {%0,%1,%2,%3}, [%4];"
                 : "=r"(r[0]), "=r"(r[1]), "=r"(r[2]), "=r"(r[3]) : "r"(addr));
}
__device__ __forceinline__ void ldsm2(uint32_t* r, uint32_t addr) {
    asm volatile("ldmatrix.sync.aligned.m8n8.x2.shared.b16 {%0,%1}, [%2];"
                 : "=r"(r[0]), "=r"(r[1]) : "r"(addr));
}
__device__ __forceinline__ void mma16816(float* c, const uint32_t* a, const uint32_t* b) {
    asm volatile("mma.sync.aligned.m16n8k16.row.col.f32.bf16.bf16.f32 "
                 "{%0,%1,%2,%3}, {%4,%5,%6,%7}, {%8,%9}, {%0,%1,%2,%3};"
                 : "+f"(c[0]), "+f"(c[1]), "+f"(c[2]), "+f"(c[3])
                 : "r"(a[0]), "r"(a[1]), "r"(a[2]), "r"(a[3]), "r"(b[0]), "r"(b[1]));
}

// ---------------- CSR build ----------------
__global__ void k_zero_cnt() {
    int i = blockIdx.x * blockDim.x + threadIdx.x;
    if (i < NN) d_cnt[i] = 0;
}
__global__ void k_count(const int* __restrict__ ei) {
    int e = blockIdx.x * blockDim.x + threadIdx.x;
    if (e < NE) atomicAdd(&d_cnt[ei[NE + e]], 1);
}
__global__ void k_scan_nodes() {
    __shared__ int buf[1024];
    __shared__ int carry;
    int tid = threadIdx.x;
    if (tid == 0) carry = 0;
    __syncthreads();
    for (int base = 0; base < NN; base += 1024) {
        int v = (base + tid < NN) ? d_cnt[base + tid] : 0;
        buf[tid] = v;
        __syncthreads();
        for (int off = 1; off < 1024; off <<= 1) {
            int t = (tid >= off) ? buf[tid - off] : 0;
            __syncthreads();
            buf[tid] += t;
            __syncthreads();
        }
        int excl = buf[tid] - v + carry;
        if (base + tid < NN) { d_rowptr[base + tid] = excl; d_cnt[base + tid] = excl; }
        __syncthreads();
        if (tid == 0) carry += buf[1023];
        __syncthreads();
    }
    if (tid == 0) d_rowptr[NN] = carry;
}
__global__ void k_scatter(const int* __restrict__ ei) {
    int e = blockIdx.x * blockDim.x + threadIdx.x;
    if (e < NE) {
        int pos = atomicAdd(&d_cnt[ei[NE + e]], 1);
        d_eids[pos] = e;
    }
}
__global__ void k_sortrows() {
    int i = blockIdx.x * blockDim.x + threadIdx.x;
    if (i >= NN) return;
    int rs = d_rowptr[i], re = d_rowptr[i + 1];
    for (int a = rs + 1; a < re; a++) {
        int key = d_eids[a];
        int b = a - 1;
        while (b >= rs && d_eids[b] > key) { d_eids[b + 1] = d_eids[b]; b--; }
        d_eids[b + 1] = key;
    }
}

// ---------------- encoder ----------------
#define ENC_NPB 64
__global__ void k_encoder(const float* __restrict__ x, const float* __restrict__ W,
                          const float* __restrict__ b) {
    __shared__ float Ws[NODE_DIM][HID];
    __shared__ float bs[HID];
    int c = threadIdx.x;
    #pragma unroll
    for (int k = 0; k < NODE_DIM; k++) Ws[k][c] = W[k * HID + c];
    bs[c] = b[c];
    __syncthreads();
    int n0 = blockIdx.x * ENC_NPB;
    for (int i = 0; i < ENC_NPB; i++) {
        int n = n0 + i;
        if (n >= NN) break;
        float acc = bs[c];
        #pragma unroll
        for (int k = 0; k < NODE_DIM; k++) acc += __ldg(&x[n * NODE_DIM + k]) * Ws[k][c];
        d_h[n * HID + c] = fmaxf(acc, 0.f);
    }
}

// ---------------- weight conversion: W -> transposed bf16 hi/lo ----------------
__global__ void k_convW(const float* __restrict__ W1, const float* __restrict__ W2) {
    int idx = blockIdx.x * blockDim.x + threadIdx.x;
    if (idx >= NLAYER * 2 * HID * HID) return;
    int e = idx & 65535;
    int lm = idx >> 16;                // l*2 + mat
    int l = lm >> 1, mat = lm & 1;
    int n = e & 255, k = e >> 8;
    const float* W = mat ? W2 : W1;
    float w = W[l * 65536 + k * 256 + n];
    __nv_bfloat16 hi = __float2bfloat16(w);
    __nv_bfloat16 lo = __float2bfloat16(w - __bfloat162float(hi));
    d_Wc[(size_t)(lm * 2 + 0) * 65536 + n * 256 + k] = hi;
    d_Wc[(size_t)(lm * 2 + 1) * 65536 + n * 256 + k] = lo;
}

// ---------------- GINE aggregation: z = h + sum relu(h[src]+e), written as bf16 hi/lo ----------------
__global__ void k_aggregate(const int* __restrict__ ei, const float* __restrict__ ea,
                            const float* __restrict__ eW, const float* __restrict__ eb) {
    __shared__ float Ws[EDGE_DIM][HID];
    __shared__ float bs[HID];
    int c = threadIdx.x;
    #pragma unroll
    for (int k = 0; k < EDGE_DIM; k++) Ws[k][c] = eW[k * HID + c];
    bs[c] = eb[c];
    __syncthreads();
    int n0 = blockIdx.x * 8;
    for (int i = 0; i < 8; i++) {
        int n = n0 + i;
        if (n >= NN) break;
        int rs = d_rowptr[n], re = d_rowptr[n + 1];
        float acc = d_h[n * HID + c];
        for (int p = rs; p < re; p++) {
            int e = d_eids[p];
            int src = ei[e];
            float ec = bs[c];
            #pragma unroll
            for (int k = 0; k < EDGE_DIM; k++) ec += __ldg(&ea[e * EDGE_DIM + k]) * Ws[k][c];
            acc += fmaxf(d_h[src * HID + c] + ec, 0.f);
        }
        __nv_bfloat16 hi = __float2bfloat16(acc);
        d_zhi[n * HID + c] = hi;
        d_zlo[n * HID + c] = __float2bfloat16(acc - __bfloat162float(hi));
    }
}

// ---------------- HMMA GEMM: D[M,256] = (Ahi+Alo)[M,256] @ (Whi+Wlo)^T + bias ----------------
// Virtual K = 768: term 0 = Ah*Wh, term 1 = Ah*Wl, term 2 = Al*Wh.
// CTA tile 128(M) x 128(N); 8 warps = 2(M) x 4(N); warp tile 64x32; k-chunk 64, double-buffered cp.async.
// MODE 0: out = relu(D+bias) split -> (Ohi, Olo). MODE 1: out = D+bias -> Of (fp32).
#define SM_BUF 32768   // 16KB A + 16KB B per buffer

__device__ __forceinline__ void g_load_chunk(
    uint32_t sb, int buf, int vk, int tid, int bm, int bn,
    const __nv_bfloat16* __restrict__ Ahi, const __nv_bfloat16* __restrict__ Alo,
    const __nv_bfloat16* __restrict__ Wc) {
    int term = vk >> 8, kk = vk & 255;
    const __nv_bfloat16* Asrc = (term == 2) ? Alo : Ahi;
    const __nv_bfloat16* Bsrc = Wc + ((term == 1) ? 65536 : 0);
    uint32_t abase = sb + buf * SM_BUF;
    uint32_t bbase = abase + 16384;
    #pragma unroll
    for (int t = 0; t < 4; t++) {
        int idx = tid + t * 256;
        int row = idx >> 3, seg = idx & 7;
        int gm = bm + row;
        cp16(abase + SW128(row * 128 + seg * 16),
             Asrc + (size_t)gm * 256 + kk + seg * 8, (gm < NN) ? 16 : 0);
    }
    #pragma unroll
    for (int t = 0; t < 4; t++) {
        int idx = tid + t * 256;
        int row = idx >> 3, seg = idx & 7;
        cp16(bbase + SW128(row * 128 + seg * 16),
             Bsrc + (size_t)(bn + row) * 256 + kk + seg * 8, 16);
    }
    CP_COMMIT();
}

template <int MODE>
__global__ __launch_bounds__(256, 2)
void k_mma_gemm(const __nv_bfloat16* __restrict__ Ahi, const __nv_bfloat16* __restrict__ Alo,
                const __nv_bfloat16* __restrict__ Wc,   // [2 hl][256 n][256 k] bf16
                const float* __restrict__ bias,
                __nv_bfloat16* __restrict__ Ohi, __nv_bfloat16* __restrict__ Olo,
                float* __restrict__ Of) {
    extern __shared__ char smem[];
    uint32_t sb = smem_u32(smem);
    int tid = threadIdx.x, wid = tid >> 5, lane = tid & 31;
    int bm = blockIdx.y * 128;
    int bn = blockIdx.x * 128;
    int wm = wid & 1, wn = wid >> 1;

    float c[4][4][4];
    #pragma unroll
    for (int mt = 0; mt < 4; mt++)
        #pragma unroll
        for (int nt = 0; nt < 4; nt++)
            #pragma unroll
            for (int q = 0; q < 4; q++) c[mt][nt][q] = 0.f;

    g_load_chunk(sb, 0, 0, tid, bm, bn, Ahi, Alo, Wc);

    #pragma unroll 1
    for (int i = 0; i < 12; i++) {
        if (i + 1 < 12) {
            g_load_chunk(sb, (i + 1) & 1, (i + 1) * 64, tid, bm, bn, Ahi, Alo, Wc);
            CP_WAIT1();
        } else {
            CP_WAIT0();
        }
        __syncthreads();
        uint32_t abase = sb + (i & 1) * SM_BUF;
        uint32_t bbase = abase + 16384;
        #pragma unroll
        for (int ks = 0; ks < 4; ks++) {
            uint32_t a[4][4], b[4][2];
            #pragma unroll
            for (int mt = 0; mt < 4; mt++) {
                int row = wm * 64 + mt * 16 + (lane & 15);
                ldsm4(a[mt], abase + SW128(row * 128 + ks * 32 + (lane >> 4) * 16));
            }
            #pragma unroll
            for (int nt = 0; nt < 4; nt++) {
                int row = wn * 32 + nt * 8 + (lane & 7);
                ldsm2(b[nt], bbase + SW128(row * 128 + ks * 32 + (((lane >> 3) & 1)) * 16));
            }
            #pragma unroll
            for (int mt = 0; mt < 4; mt++)
                #pragma unroll
                for (int nt = 0; nt < 4; nt++)
                    mma16816(c[mt][nt], a[mt], b[nt]);
        }
        __syncthreads();
    }

    // epilogue
    int gid = lane >> 2, tig = lane & 3;
    #pragma unroll
    for (int mt = 0; mt < 4; mt++) {
        #pragma unroll
        for (int nt = 0; nt < 4; nt++) {
            int col = bn + wn * 32 + nt * 8 + tig * 2;
            float b0 = __ldg(&bias[col]), b1 = __ldg(&bias[col + 1]);
            #pragma unroll
            for (int half = 0; half < 2; half++) {
                int r = bm + wm * 64 + mt * 16 + gid + half * 8;
                if (r >= NN) continue;
                float v0 = c[mt][nt][half * 2 + 0] + b0;
                float v1 = c[mt][nt][half * 2 + 1] + b1;
                if (MODE == 0) {
                    v0 = fmaxf(v0, 0.f); v1 = fmaxf(v1, 0.f);
                    __nv_bfloat16 h0 = __float2bfloat16(v0), h1 = __float2bfloat16(v1);
                    __nv_bfloat16 l0 = __float2bfloat16(v0 - __bfloat162float(h0));
                    __nv_bfloat16 l1 = __float2bfloat16(v1 - __bfloat162float(h1));
                    *(__nv_bfloat162*)(Ohi + (size_t)r * 256 + col) = __halves2bfloat162(h0, h1);
                    *(__nv_bfloat162*)(Olo + (size_t)r * 256 + col) = __halves2bfloat162(l0, l1);
                } else {
                    *(float2*)(Of + (size_t)r * 256 + col) = make_float2(v0, v1);
                }
            }
        }
    }
}

// ---------------- BatchNorm (deterministic two-level reduction) ----------------
__global__ void k_bn_partial() {
    int c = threadIdx.x;
    int n0 = blockIdx.x * 256;
    float s = 0.f, s2 = 0.f;
    for (int i = 0; i < 256; i++) {
        int n = n0 + i;
        if (n >= NN) break;
        float v = d_z[n * HID + c];
        s += v; s2 += v * v;
    }
    d_psum[blockIdx.x * HID + c] = s;
    d_psq[blockIdx.x * HID + c] = s2;
}
__global__ void k_bn_final(const float* __restrict__ g, const float* __restrict__ b) {
    int c = threadIdx.x;
    float s = 0.f, s2 = 0.f;
    for (int blk = 0; blk < NB_BN; blk++) {
        s += d_psum[blk * HID + c];
        s2 += d_psq[blk * HID + c];
    }
    float mu = s / (float)NN;
    float var = s2 / (float)NN - mu * mu;
    float sc = g[c] * rsqrtf(var + 1e-5f);
    d_scale[c] = sc;
    d_shift[c] = b[c] - mu * sc;
}
__global__ void k_bn_apply() {
    int idx = blockIdx.x * blockDim.x + threadIdx.x;
    if (idx >= NN * HID) return;
    int c = idx & (HID - 1);
    float v = d_z[idx] * d_scale[c] + d_shift[c];
    d_h[idx] = fmaxf(v, 0.f) + d_h[idx];
}

// ---------------- graph pooling ----------------
__global__ void k_zero_gcnt() {
    int i = blockIdx.x * blockDim.x + threadIdx.x;
    if (i < NG) d_gcnt[i] = 0;
}
__global__ void k_gcount(const int* __restrict__ batch) {
    int n = blockIdx.x * blockDim.x + threadIdx.x;
    if (n < NN) atomicAdd(&d_gcnt[batch[n]], 1);
}
__global__ void k_gscan() {
    __shared__ int buf[1024];
    int tid = threadIdx.x;
    int v = d_gcnt[tid];
    buf[tid] = v;
    __syncthreads();
    for (int off = 1; off < 1024; off <<= 1) {
        int t = (tid >= off) ? buf[tid - off] : 0;
        __syncthreads();
        buf[tid] += t;
        __syncthreads();
    }
    d_gstart[tid + 1] = buf[tid];
    if (tid == 0) d_gstart[0] = 0;
}
__global__ void k_pool() {
    int g = blockIdx.x, c = threadIdx.x;
    int s0 = d_gstart[g], s1 = d_gstart[g + 1];
    float sum = 0.f;
    float mx = -INFINITY;
    for (int n = s0; n < s1; n++) {
        float v = d_h[n * HID + c];
        sum += v;
        mx = fmaxf(mx, v);
    }
    float cntf = (float)(s1 - s0);
    float mean = sum / fmaxf(cntf, 1.f);
    d_gfeat[g * 768 + c] = mean;
    d_gfeat[g * 768 + 256 + c] = sum;
    d_gfeat[g * 768 + 512 + c] = mx;
}

// ---------------- head ----------------
__global__ void k_head1(const float* __restrict__ W, const float* __restrict__ b) {
    __shared__ float gs[8][768];
    int tid = threadIdx.x;
    int g0 = blockIdx.x * 8;
    for (int j = 0; j < 8; j++)
        for (int idx = tid; idx < 768; idx += 256)
            gs[j][idx] = d_gfeat[(g0 + j) * 768 + idx];
    __syncthreads();
    int c = tid;
    float acc[8];
    float bv = b[c];
    #pragma unroll
    for (int j = 0; j < 8; j++) acc[j] = bv;
    for (int k = 0; k < 768; k++) {
        float w = W[k * 256 + c];
        #pragma unroll
        for (int j = 0; j < 8; j++) acc[j] += gs[j][k] * w;
    }
    #pragma unroll
    for (int j = 0; j < 8; j++) d_h1[(g0 + j) * 256 + c] = fmaxf(acc[j], 0.f);
}
__global__ void k_head2(const float* __restrict__ W, const float* __restrict__ b) {
    __shared__ float hs[8][256];
    int tid = threadIdx.x;  // 128 threads
    int g0 = blockIdx.x * 8;
    for (int j = 0; j < 8; j++)
        for (int idx = tid; idx < 256; idx += 128)
            hs[j][idx] = d_h1[(g0 + j) * 256 + idx];
    __syncthreads();
    int c = tid;
    float acc[8];
    float bv = b[c];
    #pragma unroll
    for (int j = 0; j < 8; j++) acc[j] = bv;
    for (int k = 0; k < 256; k++) {
        float w = W[k * 128 + c];
        #pragma unroll
        for (int j = 0; j < 8; j++) acc[j] += hs[j][k] * w;
    }
    #pragma unroll
    for (int j = 0; j < 8; j++) d_h2[(g0 + j) * 128 + c] = fmaxf(acc[j], 0.f);
}
__global__ void k_head3(const float* __restrict__ W, const float* __restrict__ b,
                        float* __restrict__ out) {
    int w = threadIdx.x >> 5, lane = threadIdx.x & 31;
    int g = blockIdx.x * 8 + w;
    float s = 0.f;
    for (int k = lane; k < 128; k += 32)
        s += d_h2[g * 128 + k] * __ldg(&W[k]);
    #pragma unroll
    for (int off = 16; off; off >>= 1) s += __shfl_xor_sync(0xffffffffu, s, off);
    if (lane == 0) out[g] = s + __ldg(&b[0]);
}

// ---------------- launch ----------------
extern "C" void kernel_launch(void* const* d_in, const int* in_sizes, int n_in,
                              void* d_out, int out_size) {
    const float* x      = (const float*)d_in[0];
    const int*   ei     = (const int*)d_in[1];
    const float* ea     = (const float*)d_in[2];
    const int*   batch  = (const int*)d_in[3];
    const float* enc_W  = (const float*)d_in[4];
    const float* enc_b  = (const float*)d_in[5];
    const float* edge_W = (const float*)d_in[6];
    const float* edge_b = (const float*)d_in[7];
    const float* mlp_W1 = (const float*)d_in[8];
    const float* mlp_b1 = (const float*)d_in[9];
    const float* mlp_W2 = (const float*)d_in[10];
    const float* mlp_b2 = (const float*)d_in[11];
    const float* bn_g   = (const float*)d_in[12];
    const float* bn_b   = (const float*)d_in[13];
    const float* hW1    = (const float*)d_in[14];
    const float* hb1    = (const float*)d_in[15];
    const float* hW2    = (const float*)d_in[16];
    const float* hb2    = (const float*)d_in[17];
    const float* hW3    = (const float*)d_in[18];
    const float* hb3    = (const float*)d_in[19];
    float* out = (float*)d_out;

    static __nv_bfloat16 *p_zhi = nullptr, *p_zlo = nullptr, *p_thi = nullptr,
                         *p_tlo = nullptr, *p_Wc = nullptr;
    static float* p_z = nullptr;
    if (!p_zhi) {
        cudaGetSymbolAddress((void**)&p_zhi, d_zhi);
        cudaGetSymbolAddress((void**)&p_zlo, d_zlo);
        cudaGetSymbolAddress((void**)&p_thi, d_thi);
        cudaGetSymbolAddress((void**)&p_tlo, d_tlo);
        cudaGetSymbolAddress((void**)&p_Wc, d_Wc);
        cudaGetSymbolAddress((void**)&p_z, d_z);
        cudaFuncSetAttribute(k_mma_gemm<0>, cudaFuncAttributeMaxDynamicSharedMemorySize, 2 * SM_BUF);
        cudaFuncSetAttribute(k_mma_gemm<1>, cudaFuncAttributeMaxDynamicSharedMemorySize, 2 * SM_BUF);
    }

    // weight conversion (deterministic, every call)
    k_convW<<<(NLAYER * 2 * HID * HID + 255) / 256, 256>>>(mlp_W1, mlp_W2);

    // CSR build (deterministic)
    k_zero_cnt<<<(NN + 255) / 256, 256>>>();
    k_count<<<(NE + 255) / 256, 256>>>(ei);
    k_scan_nodes<<<1, 1024>>>();
    k_scatter<<<(NE + 255) / 256, 256>>>(ei);
    k_sortrows<<<(NN + 255) / 256, 256>>>();

    // encoder
    k_encoder<<<(NN + ENC_NPB - 1) / ENC_NPB, 256>>>(x, enc_W, enc_b);

    dim3 gemm_grid(2, (NN + 127) / 128);   // (N/128, M/128)
    for (int l = 0; l < NLAYER; l++) {
        k_aggregate<<<(NN + 7) / 8, 256>>>(ei, ea, edge_W + l * EDGE_DIM * HID,
                                           edge_b + l * HID);
        const __nv_bfloat16* W1c = p_Wc + (size_t)(l * 2 + 0) * 2 * 65536;
        const __nv_bfloat16* W2c = p_Wc + (size_t)(l * 2 + 1) * 2 * 65536;
        k_mma_gemm<0><<<gemm_grid, 256, 2 * SM_BUF>>>(p_zhi, p_zlo, W1c, mlp_b1 + l * HID,
                                                      p_thi, p_tlo, nullptr);
        k_mma_gemm<1><<<gemm_grid, 256, 2 * SM_BUF>>>(p_thi, p_tlo, W2c, mlp_b2 + l * HID,
                                                      nullptr, nullptr, p_z);
        k_bn_partial<<<NB_BN, 256>>>();
        k_bn_final<<<1, 256>>>(bn_g + l * HID, bn_b + l * HID);
        k_bn_apply<<<(NN * HID + 255) / 256, 256>>>();
    }

    // pooling + head
    k_zero_gcnt<<<(NG + 255) / 256, 256>>>();
    k_gcount<<<(NN + 255) / 256, 256>>>(batch);
    k_gscan<<<1, 1024>>>();
    k_pool<<<NG, 256>>>();
    k_head1<<<NG / 8, 256>>>(hW1, hb1);
    k_head2<<<NG / 8, 128>>>(hW2, hb2);
    k_head3<<<NG / 8, 256>>>(hW3, hb3, out);
}

// round 4
// speedup vs baseline: 1.7399x; 1.1168x over previous
#include <cuda_runtime.h>
#include <cuda_bf16.h>
#include <math.h>
#include <stdint.h>

#define NN 50000
#define NE 300000
#define HID 256
#define NLAYER 4
#define NG 1024
#define NODE_DIM 11
#define EDGE_DIM 5
#define NSB ((NN + 255) / 256)    // 196 scan blocks
#define NMB ((NN + 127) / 128)    // 391 GEMM M-blocks

// ---------------- persistent scratch (device globals; no allocation) ----------------
__device__ __align__(16) float d_h[NN * HID];
__device__ __align__(16) float d_z[NN * HID];            // GEMM2 out (fp32, for BN)
__device__ __align__(16) __nv_bfloat16 d_zhi[NN * HID];  // GEMM1 input hi
__device__ __align__(16) __nv_bfloat16 d_zlo[NN * HID];
__device__ __align__(16) __nv_bfloat16 d_thi[NN * HID];  // GEMM2 input hi
__device__ __align__(16) __nv_bfloat16 d_tlo[NN * HID];
__device__ __align__(16) __nv_bfloat16 d_Wc[NLAYER * 2 * 2 * HID * HID]; // [l][mat][hl][n][k]
__device__ int   d_cnt[NN];
__device__ int   d_rowptr[NN + 1];
__device__ int   d_eids[NE];
__device__ int   d_bsums[NSB];
__device__ int   d_boff[NSB];
__device__ float d_psum[NMB * HID];
__device__ float d_psq[NMB * HID];
__device__ float d_scale[HID];
__device__ float d_shift[HID];
__device__ int   d_gstart[NG + 1];
__device__ float d_gfeat[NG * 3 * HID];
__device__ float d_h1[NG * HID];
__device__ float d_h2[NG * (HID / 2)];

// ================= portable PTX helpers (sm_80+ baseline; NO tcgen05) =================
__device__ __forceinline__ uint32_t smem_u32(const void* p) {
    uint32_t a;
    asm("{ .reg .u64 t; cvta.to.shared.u64 t, %1; cvt.u32.u64 %0, t; }" : "=r"(a) : "l"(p));
    return a;
}
#define SW128(x) ((x) ^ (((x) >> 3) & 0x70))

__device__ __forceinline__ void cp16(uint32_t dst, const void* src, int srcbytes) {
    asm volatile("cp.async.cg.shared.global [%0], [%1], 16, %2;"
                 :: "r"(dst), "l"(src), "r"(srcbytes) : "memory");
}
#define CP_COMMIT() asm volatile("cp.async.commit_group;" ::: "memory")
#define CP_WAIT0()  asm volatile("cp.async.wait_group 0;" ::: "memory")
#define CP_WAIT1()  asm volatile("cp.async.wait_group 1;" ::: "memory")

__device__ __forceinline__ void ldsm4(uint32_t* r, uint32_t addr) {
    asm volatile("ldmatrix.sync.aligned.m8n8.x4.shared.b16 {%0,%1,%2,%3}, [%4];"
                 : "=r"(r[0]), "=r"(r[1]), "=r"(r[2]), "=r"(r[3]) : "r"(addr));
}
__device__ __forceinline__ void mma16816(float* c, const uint32_t* a, const uint32_t* b) {
    asm volatile("mma.sync.aligned.m16n8k16.row.col.f32.bf16.bf16.f32 "
                 "{%0,%1,%2,%3}, {%4,%5,%6,%7}, {%8,%9}, {%0,%1,%2,%3};"
                 : "+f"(c[0]), "+f"(c[1]), "+f"(c[2]), "+f"(c[3])
                 : "r"(a[0]), "r"(a[1]), "r"(a[2]), "r"(a[3]), "r"(b[0]), "r"(b[1]));
}

// ---------------- CSR build ----------------
__global__ void k_zero_cnt() {
    int i = blockIdx.x * blockDim.x + threadIdx.x;
    if (i < NN) d_cnt[i] = 0;
}
__global__ void k_count(const int* __restrict__ ei) {
    int e = blockIdx.x * blockDim.x + threadIdx.x;
    if (e < NE) atomicAdd(&d_cnt[ei[NE + e]], 1);
}
// two-level scan: block sums -> scan sums -> block-local scan + offset
__global__ void k_bsum() {
    __shared__ int red[256];
    int tid = threadIdx.x;
    int i = blockIdx.x * 256 + tid;
    red[tid] = (i < NN) ? d_cnt[i] : 0;
    __syncthreads();
    for (int off = 128; off; off >>= 1) {
        if (tid < off) red[tid] += red[tid + off];
        __syncthreads();
    }
    if (tid == 0) d_bsums[blockIdx.x] = red[0];
}
__global__ void k_bscan() {
    __shared__ int buf[256];
    int tid = threadIdx.x;
    int v = (tid < NSB) ? d_bsums[tid] : 0;
    buf[tid] = v;
    __syncthreads();
    for (int off = 1; off < 256; off <<= 1) {
        int t = (tid >= off) ? buf[tid - off] : 0;
        __syncthreads();
        buf[tid] += t;
        __syncthreads();
    }
    if (tid < NSB) d_boff[tid] = buf[tid] - v;   // exclusive
    if (tid == 0) d_rowptr[NN] = NE;
}
__global__ void k_badd() {
    __shared__ int buf[256];
    int tid = threadIdx.x;
    int i = blockIdx.x * 256 + tid;
    int v = (i < NN) ? d_cnt[i] : 0;
    buf[tid] = v;
    __syncthreads();
    for (int off = 1; off < 256; off <<= 1) {
        int t = (tid >= off) ? buf[tid - off] : 0;
        __syncthreads();
        buf[tid] += t;
        __syncthreads();
    }
    if (i < NN) {
        int excl = buf[tid] - v + d_boff[blockIdx.x];
        d_rowptr[i] = excl;
        d_cnt[i] = excl;   // scatter cursor
    }
}
__global__ void k_scatter(const int* __restrict__ ei) {
    int e = blockIdx.x * blockDim.x + threadIdx.x;
    if (e < NE) {
        int pos = atomicAdd(&d_cnt[ei[NE + e]], 1);
        d_eids[pos] = e;
    }
}
__global__ void k_sortrows() {
    int i = blockIdx.x * blockDim.x + threadIdx.x;
    if (i >= NN) return;
    int rs = d_rowptr[i], re = d_rowptr[i + 1];
    for (int a = rs + 1; a < re; a++) {
        int key = d_eids[a];
        int b = a - 1;
        while (b >= rs && d_eids[b] > key) { d_eids[b + 1] = d_eids[b]; b--; }
        d_eids[b + 1] = key;
    }
}

// ---------------- encoder ----------------
#define ENC_NPB 64
__global__ void k_encoder(const float* __restrict__ x, const float* __restrict__ W,
                          const float* __restrict__ b) {
    __shared__ float Ws[NODE_DIM][HID];
    __shared__ float bs[HID];
    int c = threadIdx.x;
    #pragma unroll
    for (int k = 0; k < NODE_DIM; k++) Ws[k][c] = W[k * HID + c];
    bs[c] = b[c];
    __syncthreads();
    int n0 = blockIdx.x * ENC_NPB;
    for (int i = 0; i < ENC_NPB; i++) {
        int n = n0 + i;
        if (n >= NN) break;
        float acc = bs[c];
        #pragma unroll
        for (int k = 0; k < NODE_DIM; k++) acc += __ldg(&x[n * NODE_DIM + k]) * Ws[k][c];
        d_h[n * HID + c] = fmaxf(acc, 0.f);
    }
}

// ---------------- weight conversion: W -> transposed bf16 hi/lo ----------------
__global__ void k_convW(const float* __restrict__ W1, const float* __restrict__ W2) {
    int idx = blockIdx.x * blockDim.x + threadIdx.x;
    if (idx >= NLAYER * 2 * HID * HID) return;
    int e = idx & 65535;
    int lm = idx >> 16;                // l*2 + mat
    int l = lm >> 1, mat = lm & 1;
    int n = e & 255, k = e >> 8;
    const float* W = mat ? W2 : W1;
    float w = W[l * 65536 + k * 256 + n];
    __nv_bfloat16 hi = __float2bfloat16(w);
    __nv_bfloat16 lo = __float2bfloat16(w - __bfloat162float(hi));
    d_Wc[(size_t)(lm * 2 + 0) * 65536 + n * 256 + k] = hi;
    d_Wc[(size_t)(lm * 2 + 1) * 65536 + n * 256 + k] = lo;
}

// ---------------- GINE aggregation: z = h + sum relu(h[src]+e), written as bf16 hi/lo ----------------
__global__ void k_aggregate(const int* __restrict__ ei, const float* __restrict__ ea,
                            const float* __restrict__ eW, const float* __restrict__ eb) {
    __shared__ float Ws[EDGE_DIM][HID];
    __shared__ float bs[HID];
    int c = threadIdx.x;
    #pragma unroll
    for (int k = 0; k < EDGE_DIM; k++) Ws[k][c] = eW[k * HID + c];
    bs[c] = eb[c];
    __syncthreads();
    int n0 = blockIdx.x * 8;
    for (int i = 0; i < 8; i++) {
        int n = n0 + i;
        if (n >= NN) break;
        int rs = d_rowptr[n], re = d_rowptr[n + 1];
        float acc = d_h[n * HID + c];
        for (int p = rs; p < re; p++) {
            int e = d_eids[p];
            int src = ei[e];
            float ec = bs[c];
            #pragma unroll
            for (int k = 0; k < EDGE_DIM; k++) ec += __ldg(&ea[e * EDGE_DIM + k]) * Ws[k][c];
            acc += fmaxf(d_h[src * HID + c] + ec, 0.f);
        }
        __nv_bfloat16 hi = __float2bfloat16(acc);
        d_zhi[n * HID + c] = hi;
        d_zlo[n * HID + c] = __float2bfloat16(acc - __bfloat162float(hi));
    }
}

// ---------------- HMMA GEMM: D[M,256] = (Ahi+Alo)[M,256] @ (Whi+Wlo)^T + bias ----------------
// Virtual K = 768: term 0 = Ah*Wh, term 1 = Ah*Wl, term 2 = Al*Wh.
// CTA tile 128x128; 8 warps = 2(M) x 4(N); warp tile 64x32; k-chunk 64, double-buffered cp.async.
// MODE 0: out = relu(D+bias) split -> (Ohi, Olo). MODE 1: out = D+bias -> Of (fp32) + BN partial stats.
#define SM_BUF 32768   // 16KB A + 16KB B per buffer

__device__ __forceinline__ void g_load_chunk(
    uint32_t sb, int buf, int vk, int tid, int bm, int bn,
    const __nv_bfloat16* __restrict__ Ahi, const __nv_bfloat16* __restrict__ Alo,
    const __nv_bfloat16* __restrict__ Wc) {
    int term = vk >> 8, kk = vk & 255;
    const __nv_bfloat16* Asrc = (term == 2) ? Alo : Ahi;
    const __nv_bfloat16* Bsrc = Wc + ((term == 1) ? 65536 : 0);
    uint32_t abase = sb + buf * SM_BUF;
    uint32_t bbase = abase + 16384;
    #pragma unroll
    for (int t = 0; t < 4; t++) {
        int idx = tid + t * 256;
        int row = idx >> 3, seg = idx & 7;
        int gm = bm + row;
        cp16(abase + SW128(row * 128 + seg * 16),
             Asrc + (size_t)gm * 256 + kk + seg * 8, (gm < NN) ? 16 : 0);
    }
    #pragma unroll
    for (int t = 0; t < 4; t++) {
        int idx = tid + t * 256;
        int row = idx >> 3, seg = idx & 7;
        cp16(bbase + SW128(row * 128 + seg * 16),
             Bsrc + (size_t)(bn + row) * 256 + kk + seg * 8, 16);
    }
    CP_COMMIT();
}

template <int MODE>
__global__ __launch_bounds__(256, 2)
void k_mma_gemm(const __nv_bfloat16* __restrict__ Ahi, const __nv_bfloat16* __restrict__ Alo,
                const __nv_bfloat16* __restrict__ Wc,   // [2 hl][256 n][256 k] bf16
                const float* __restrict__ bias,
                __nv_bfloat16* __restrict__ Ohi, __nv_bfloat16* __restrict__ Olo,
                float* __restrict__ Of) {
    extern __shared__ char smem[];
    uint32_t sb = smem_u32(smem);
    int tid = threadIdx.x, wid = tid >> 5, lane = tid & 31;
    int bm = blockIdx.y * 128;
    int bn = blockIdx.x * 128;
    int wm = wid & 1, wn = wid >> 1;

    float c[4][4][4];
    #pragma unroll
    for (int mt = 0; mt < 4; mt++)
        #pragma unroll
        for (int nt = 0; nt < 4; nt++)
            #pragma unroll
            for (int q = 0; q < 4; q++) c[mt][nt][q] = 0.f;

    g_load_chunk(sb, 0, 0, tid, bm, bn, Ahi, Alo, Wc);

    #pragma unroll 1
    for (int i = 0; i < 12; i++) {
        if (i + 1 < 12) {
            g_load_chunk(sb, (i + 1) & 1, (i + 1) * 64, tid, bm, bn, Ahi, Alo, Wc);
            CP_WAIT1();
        } else {
            CP_WAIT0();
        }
        __syncthreads();
        uint32_t abase = sb + (i & 1) * SM_BUF;
        uint32_t bbase = abase + 16384;
        #pragma unroll
        for (int ks = 0; ks < 4; ks++) {
            uint32_t a[4][4], b[4][2];
            #pragma unroll
            for (int mt = 0; mt < 4; mt++) {
                int row = wm * 64 + mt * 16 + (lane & 15);
                ldsm4(a[mt], abase + SW128(row * 128 + ks * 32 + (lane >> 4) * 16));
            }
            #pragma unroll
            for (int p = 0; p < 2; p++) {   // ldsm4 fetches two 8-col n-tiles + both k-halves
                uint32_t r4[4];
                int row = wn * 32 + (p * 2 + (lane >> 4)) * 8 + (lane & 7);
                ldsm4(r4, bbase + SW128(row * 128 + ks * 32 + ((lane >> 3) & 1) * 16));
                b[2 * p + 0][0] = r4[0]; b[2 * p + 0][1] = r4[1];
                b[2 * p + 1][0] = r4[2]; b[2 * p + 1][1] = r4[3];
            }
            #pragma unroll
            for (int mt = 0; mt < 4; mt++)
                #pragma unroll
                for (int nt = 0; nt < 4; nt++)
                    mma16816(c[mt][nt], a[mt], b[nt]);
        }
        __syncthreads();
    }

    // epilogue
    int gid = lane >> 2, tig = lane & 3;
    float s[8], s2[8];
    if (MODE == 1) {
        #pragma unroll
        for (int j = 0; j < 8; j++) { s[j] = 0.f; s2[j] = 0.f; }
    }
    #pragma unroll
    for (int mt = 0; mt < 4; mt++) {
        #pragma unroll
        for (int nt = 0; nt < 4; nt++) {
            int col = bn + wn * 32 + nt * 8 + tig * 2;
            float b0 = __ldg(&bias[col]), b1 = __ldg(&bias[col + 1]);
            #pragma unroll
            for (int half = 0; half < 2; half++) {
                int r = bm + wm * 64 + mt * 16 + gid + half * 8;
                if (r >= NN) continue;
                float v0 = c[mt][nt][half * 2 + 0] + b0;
                float v1 = c[mt][nt][half * 2 + 1] + b1;
                if (MODE == 0) {
                    v0 = fmaxf(v0, 0.f); v1 = fmaxf(v1, 0.f);
                    __nv_bfloat16 h0 = __float2bfloat16(v0), h1 = __float2bfloat16(v1);
                    __nv_bfloat16 l0 = __float2bfloat16(v0 - __bfloat162float(h0));
                    __nv_bfloat16 l1 = __float2bfloat16(v1 - __bfloat162float(h1));
                    *(__nv_bfloat162*)(Ohi + (size_t)r * 256 + col) = __halves2bfloat162(h0, h1);
                    *(__nv_bfloat162*)(Olo + (size_t)r * 256 + col) = __halves2bfloat162(l0, l1);
                } else {
                    *(float2*)(Of + (size_t)r * 256 + col) = make_float2(v0, v1);
                    s[nt * 2 + 0] += v0; s2[nt * 2 + 0] += v0 * v0;
                    s[nt * 2 + 1] += v1; s2[nt * 2 + 1] += v1 * v1;
                }
            }
        }
    }
    if (MODE == 1) {
        // reduce over gid lanes (deterministic shfl tree), then across wm via smem
        #pragma unroll
        for (int j = 0; j < 8; j++) {
            #pragma unroll
            for (int off = 4; off < 32; off <<= 1) {
                s[j]  += __shfl_xor_sync(0xffffffffu, s[j], off);
                s2[j] += __shfl_xor_sync(0xffffffffu, s2[j], off);
            }
        }
        float* ss  = (float*)smem;          // [2][128]
        float* ssq = ss + 256;              // [2][128]
        if (gid == 0) {
            #pragma unroll
            for (int nt = 0; nt < 4; nt++) {
                #pragma unroll
                for (int q = 0; q < 2; q++) {
                    int cl = wn * 32 + nt * 8 + tig * 2 + q;
                    ss[wm * 128 + cl]  = s[nt * 2 + q];
                    ssq[wm * 128 + cl] = s2[nt * 2 + q];
                }
            }
        }
        __syncthreads();
        if (tid < 128) {
            int slot = blockIdx.y * 256 + bn + tid;
            d_psum[slot] = ss[tid] + ss[128 + tid];
            d_psq[slot]  = ssq[tid] + ssq[128 + tid];
        }
    }
}

// ---------------- BatchNorm finalize + apply ----------------
__global__ void k_bn_final(const float* __restrict__ g, const float* __restrict__ b) {
    int c = threadIdx.x;
    float s = 0.f, s2 = 0.f;
    for (int blk = 0; blk < NMB; blk++) {
        s += d_psum[blk * HID + c];
        s2 += d_psq[blk * HID + c];
    }
    float mu = s / (float)NN;
    float var = s2 / (float)NN - mu * mu;
    float sc = g[c] * rsqrtf(var + 1e-5f);
    d_scale[c] = sc;
    d_shift[c] = b[c] - mu * sc;
}
__global__ void k_bn_apply() {
    int idx = blockIdx.x * blockDim.x + threadIdx.x;   // float4 index
    if (idx >= NN * 64) return;
    int c4 = idx & 63;
    float4 z = *(const float4*)(d_z + idx * 4);
    float4 h = *(const float4*)(d_h + idx * 4);
    float4 sc = *(const float4*)(d_scale + c4 * 4);
    float4 sh = *(const float4*)(d_shift + c4 * 4);
    h.x += fmaxf(z.x * sc.x + sh.x, 0.f);
    h.y += fmaxf(z.y * sc.y + sh.y, 0.f);
    h.z += fmaxf(z.z * sc.z + sh.z, 0.f);
    h.w += fmaxf(z.w * sc.w + sh.w, 0.f);
    *(float4*)(d_h + idx * 4) = h;
}

// ---------------- graph pooling ----------------
__global__ void k_gbounds(const int* __restrict__ batch) {
    int g = blockIdx.x * blockDim.x + threadIdx.x;
    if (g > NG) return;
    if (g == NG) { d_gstart[NG] = NN; return; }
    // lower_bound: first idx with batch[idx] >= g
    int lo = 0, hi = NN;
    while (lo < hi) {
        int mid = (lo + hi) >> 1;
        if (batch[mid] < g) lo = mid + 1; else hi = mid;
    }
    d_gstart[g] = lo;
}
__global__ void k_pool() {
    int g = blockIdx.x, c = threadIdx.x;
    int s0 = d_gstart[g], s1 = d_gstart[g + 1];
    float sum = 0.f;
    float mx = -INFINITY;
    for (int n = s0; n < s1; n++) {
        float v = d_h[n * HID + c];
        sum += v;
        mx = fmaxf(mx, v);
    }
    float cntf = (float)(s1 - s0);
    float mean = sum / fmaxf(cntf, 1.f);
    d_gfeat[g * 768 + c] = mean;
    d_gfeat[g * 768 + 256 + c] = sum;
    d_gfeat[g * 768 + 512 + c] = mx;
}

// ---------------- head ----------------
__global__ void k_head1(const float* __restrict__ W, const float* __restrict__ b) {
    __shared__ float gs[8][768];
    int tid = threadIdx.x;
    int g0 = blockIdx.x * 8;
    for (int j = 0; j < 8; j++)
        for (int idx = tid; idx < 768; idx += 256)
            gs[j][idx] = d_gfeat[(g0 + j) * 768 + idx];
    __syncthreads();
    int c = tid;
    float acc[8];
    float bv = b[c];
    #pragma unroll
    for (int j = 0; j < 8; j++) acc[j] = bv;
    for (int k = 0; k < 768; k++) {
        float w = W[k * 256 + c];
        #pragma unroll
        for (int j = 0; j < 8; j++) acc[j] += gs[j][k] * w;
    }
    #pragma unroll
    for (int j = 0; j < 8; j++) d_h1[(g0 + j) * 256 + c] = fmaxf(acc[j], 0.f);
}
__global__ void k_head2(const float* __restrict__ W, const float* __restrict__ b) {
    __shared__ float hs[8][256];
    int tid = threadIdx.x;  // 128 threads
    int g0 = blockIdx.x * 8;
    for (int j = 0; j < 8; j++)
        for (int idx = tid; idx < 256; idx += 128)
            hs[j][idx] = d_h1[(g0 + j) * 256 + idx];
    __syncthreads();
    int c = tid;
    float acc[8];
    float bv = b[c];
    #pragma unroll
    for (int j = 0; j < 8; j++) acc[j] = bv;
    for (int k = 0; k < 256; k++) {
        float w = W[k * 128 + c];
        #pragma unroll
        for (int j = 0; j < 8; j++) acc[j] += hs[j][k] * w;
    }
    #pragma unroll
    for (int j = 0; j < 8; j++) d_h2[(g0 + j) * 128 + c] = fmaxf(acc[j], 0.f);
}
__global__ void k_head3(const float* __restrict__ W, const float* __restrict__ b,
                        float* __restrict__ out) {
    int w = threadIdx.x >> 5, lane = threadIdx.x & 31;
    int g = blockIdx.x * 8 + w;
    float s = 0.f;
    for (int k = lane; k < 128; k += 32)
        s += d_h2[g * 128 + k] * __ldg(&W[k]);
    #pragma unroll
    for (int off = 16; off; off >>= 1) s += __shfl_xor_sync(0xffffffffu, s, off);
    if (lane == 0) out[g] = s + __ldg(&b[0]);
}

// ---------------- launch ----------------
extern "C" void kernel_launch(void* const* d_in, const int* in_sizes, int n_in,
                              void* d_out, int out_size) {
    const float* x      = (const float*)d_in[0];
    const int*   ei     = (const int*)d_in[1];
    const float* ea     = (const float*)d_in[2];
    const int*   batch  = (const int*)d_in[3];
    const float* enc_W  = (const float*)d_in[4];
    const float* enc_b  = (const float*)d_in[5];
    const float* edge_W = (const float*)d_in[6];
    const float* edge_b = (const float*)d_in[7];
    const float* mlp_W1 = (const float*)d_in[8];
    const float* mlp_b1 = (const float*)d_in[9];
    const float* mlp_W2 = (const float*)d_in[10];
    const float* mlp_b2 = (const float*)d_in[11];
    const float* bn_g   = (const float*)d_in[12];
    const float* bn_b   = (const float*)d_in[13];
    const float* hW1    = (const float*)d_in[14];
    const float* hb1    = (const float*)d_in[15];
    const float* hW2    = (const float*)d_in[16];
    const float* hb2    = (const float*)d_in[17];
    const float* hW3    = (const float*)d_in[18];
    const float* hb3    = (const float*)d_in[19];
    float* out = (float*)d_out;

    static __nv_bfloat16 *p_zhi = nullptr, *p_zlo = nullptr, *p_thi = nullptr,
                         *p_tlo = nullptr, *p_Wc = nullptr;
    static float* p_z = nullptr;
    if (!p_zhi) {
        cudaGetSymbolAddress((void**)&p_zhi, d_zhi);
        cudaGetSymbolAddress((void**)&p_zlo, d_zlo);
        cudaGetSymbolAddress((void**)&p_thi, d_thi);
        cudaGetSymbolAddress((void**)&p_tlo, d_tlo);
        cudaGetSymbolAddress((void**)&p_Wc, d_Wc);
        cudaGetSymbolAddress((void**)&p_z, d_z);
        cudaFuncSetAttribute(k_mma_gemm<0>, cudaFuncAttributeMaxDynamicSharedMemorySize, 2 * SM_BUF);
        cudaFuncSetAttribute(k_mma_gemm<1>, cudaFuncAttributeMaxDynamicSharedMemorySize, 2 * SM_BUF);
    }

    // weight conversion (deterministic, every call)
    k_convW<<<(NLAYER * 2 * HID * HID + 255) / 256, 256>>>(mlp_W1, mlp_W2);

    // CSR build (deterministic)
    k_zero_cnt<<<(NN + 255) / 256, 256>>>();
    k_count<<<(NE + 255) / 256, 256>>>(ei);
    k_bsum<<<NSB, 256>>>();
    k_bscan<<<1, 256>>>();
    k_badd<<<NSB, 256>>>();
    k_scatter<<<(NE + 255) / 256, 256>>>(ei);
    k_sortrows<<<(NN + 255) / 256, 256>>>();

    // encoder
    k_encoder<<<(NN + ENC_NPB - 1) / ENC_NPB, 256>>>(x, enc_W, enc_b);

    dim3 gemm_grid(2, NMB);   // (N/128, M/128)
    for (int l = 0; l < NLAYER; l++) {
        k_aggregate<<<(NN + 7) / 8, 256>>>(ei, ea, edge_W + l * EDGE_DIM * HID,
                                           edge_b + l * HID);
        const __nv_bfloat16* W1c = p_Wc + (size_t)(l * 2 + 0) * 2 * 65536;
        const __nv_bfloat16* W2c = p_Wc + (size_t)(l * 2 + 1) * 2 * 65536;
        k_mma_gemm<0><<<gemm_grid, 256, 2 * SM_BUF>>>(p_zhi, p_zlo, W1c, mlp_b1 + l * HID,
                                                      p_thi, p_tlo, nullptr);
        k_mma_gemm<1><<<gemm_grid, 256, 2 * SM_BUF>>>(p_thi, p_tlo, W2c, mlp_b2 + l * HID,
                                                      nullptr, nullptr, p_z);
        k_bn_final<<<1, 256>>>(bn_g + l * HID, bn_b + l * HID);
        k_bn_apply<<<(NN * 64 + 255) / 256, 256>>>();
    }

    // pooling + head
    k_gbounds<<<(NG + 256) / 256, 256>>>(batch);
    k_pool<<<NG, 256>>>();
    k_head1<<<NG / 8, 256>>>(hW1, hb1);
    k_head2<<<NG / 8, 128>>>(hW2, hb2);
    k_head3<<<NG / 8, 256>>>(hW3, hb3, out);
}